// round 5
// baseline (speedup 1.0000x reference)
#include <cuda_runtime.h>

// RoPE, float4-vectorized, MUFU trig with exact 2-term Cody-Waite reduction.
//   freq_j = 10000^(-j/32)  (correctly-rounded via double exp2, once per block)
//   ang    = fp32(p) * freq_j
//   reduce to [-pi,pi]; s=__sinf, c=__cosf (MUFU)
//   pair rotation: (c*x0 - s*x1, s*x0 + c*x1)
//
// Mapping: flat over float4 elements (2 pairs each). 2 float4 per thread,
// strided by total thread count for coalescing. Single wave of 1024 blocks.

#define PAIRS 32
#define TPB 256
#define ELEMS_PER_THREAD 2

// log2(10000)/32
#define L2_THETA_OVER_32 0.41524101186092028
#define INV_2PI 0.15915493667125702f
#define TWO_PI_C1 6.28125f
#define TWO_PI_C2 1.9353071795864769e-3f
#define RND_MAGIC 12582912.0f

__device__ __forceinline__ void fast_sincos(float ang, float& s, float& c) {
    float t = __fmaf_rn(ang, INV_2PI, RND_MAGIC);
    float k = t - RND_MAGIC;
    float r = __fmaf_rn(k, -TWO_PI_C1, ang);
    r = __fmaf_rn(k, -TWO_PI_C2, r);
    s = __sinf(r);
    c = __cosf(r);
}

__global__ void __launch_bounds__(TPB) rope_f4_kernel(
    const float4* __restrict__ x4,
    const int* __restrict__ pos,
    float4* __restrict__ o4,
    int n_f4)               // n_tokens * 16
{
    __shared__ float sh_freq[PAIRS];
    if (threadIdx.x < PAIRS) {
        sh_freq[threadIdx.x] =
            (float)exp2(-(double)threadIdx.x * L2_THETA_OVER_32);
    }
    __syncthreads();

    int tid = blockIdx.x * TPB + threadIdx.x;
    int stride = gridDim.x * TPB;

    // Batch all loads for both elements up front (MLP=4 front LDGs).
    int g[ELEMS_PER_THREAD];
    int p[ELEMS_PER_THREAD];
    float4 xv[ELEMS_PER_THREAD];
    bool valid[ELEMS_PER_THREAD];

#pragma unroll
    for (int k = 0; k < ELEMS_PER_THREAD; k++) {
        g[k] = tid + k * stride;
        valid[k] = g[k] < n_f4;
    }
#pragma unroll
    for (int k = 0; k < ELEMS_PER_THREAD; k++)
        if (valid[k]) p[k] = __ldg(&pos[g[k] >> 4]);
#pragma unroll
    for (int k = 0; k < ELEMS_PER_THREAD; k++)
        if (valid[k]) xv[k] = __ldg(&x4[g[k]]);

#pragma unroll
    for (int k = 0; k < ELEMS_PER_THREAD; k++) {
        if (!valid[k]) continue;
        int q = (g[k] & 15) << 1;          // first pair index of this float4
        float fp = (float)p[k];
        float ang0 = __fmul_rn(fp, sh_freq[q]);
        float ang1 = __fmul_rn(fp, sh_freq[q + 1]);
        float s0, c0, s1, c1;
        fast_sincos(ang0, s0, c0);
        fast_sincos(ang1, s1, c1);
        float4 ov;
        ov.x = c0 * xv[k].x - s0 * xv[k].y;
        ov.y = s0 * xv[k].x + c0 * xv[k].y;
        ov.z = c1 * xv[k].z - s1 * xv[k].w;
        ov.w = s1 * xv[k].z + c1 * xv[k].w;
        o4[g[k]] = ov;
    }
}

extern "C" void kernel_launch(void* const* d_in, const int* in_sizes, int n_in,
                              void* d_out, int out_size) {
    const float4* x4  = (const float4*)d_in[0];  // (4, 8192, 64) f32 -> float4 view
    const int*    pos = (const int*)d_in[1];     // (4, 8192) i32
    // d_in[2] = rope_buffer — unused (trig recomputed on the fly)
    float4* o4 = (float4*)d_out;

    int n_tokens = in_sizes[1];                  // 32768
    int n_f4 = n_tokens * 16;                    // 524288 float4 elements
    int threads_needed = (n_f4 + ELEMS_PER_THREAD - 1) / ELEMS_PER_THREAD;
    int grid = (threads_needed + TPB - 1) / TPB; // 1024

    rope_f4_kernel<<<grid, TPB>>>(x4, pos, o4, n_f4);
}